// round 5
// baseline (speedup 1.0000x reference)
#include <cuda_runtime.h>
#include <math.h>

// Problem constants
#define BB 4
#define TT 2048
#define DD 1024
#define HH 16
#define DHH 64
#define NQKV (3 * DD)

// Scratch: __device__ globals (allocation-free rule).
// Q,K,V in (B,H,T,DH) layout; Y in (B,T,C) layout.
__device__ float g_Q[BB * HH * TT * DHH];
__device__ float g_K[BB * HH * TT * DHH];
__device__ float g_V[BB * HH * TT * DHH];
__device__ float g_Y[BB * TT * DD];

// ---------------------------------------------------------------------------
// SGEMM C = A @ W^T (+bias), A: (M,K) row-major, W: (N,K) row-major.
// 128x128 block tile, K-tile 8, 256 threads, 8x8 per-thread register tile.
// MODE 0: scatter epilogue into Q/K/V (B,H,T,DH) with bias.
// MODE 1: plain C[m*N+n] = acc + bias[n].
// ---------------------------------------------------------------------------
template <int MODE>
__global__ __launch_bounds__(256, 2)
void gemm_xwT(const float* __restrict__ A, const float* __restrict__ W,
              const float* __restrict__ bias, float* __restrict__ C,
              float* __restrict__ Qo, float* __restrict__ Ko, float* __restrict__ Vo,
              int M, int N, int K)
{
    __shared__ float As[8][128];
    __shared__ float Bs[8][128];

    const int tid = threadIdx.x;
    const int m0 = blockIdx.y * 128;
    const int n0 = blockIdx.x * 128;
    const int tx = tid & 15;        // 0..15  -> n sub-tile
    const int ty = tid >> 4;        // 0..15  -> m sub-tile

    const int lrow = tid >> 1;      // 0..127
    const int lk4  = (tid & 1) * 4; // 0 or 4

    const float* Aptr = A + (size_t)(m0 + lrow) * K + lk4;
    const float* Wptr = W + (size_t)(n0 + lrow) * K + lk4;

    float acc[8][8];
    #pragma unroll
    for (int i = 0; i < 8; i++)
        #pragma unroll
        for (int j = 0; j < 8; j++) acc[i][j] = 0.f;

    for (int k0 = 0; k0 < K; k0 += 8) {
        float4 av = *(const float4*)(Aptr + k0);
        float4 wv = *(const float4*)(Wptr + k0);
        As[lk4 + 0][lrow] = av.x; As[lk4 + 1][lrow] = av.y;
        As[lk4 + 2][lrow] = av.z; As[lk4 + 3][lrow] = av.w;
        Bs[lk4 + 0][lrow] = wv.x; Bs[lk4 + 1][lrow] = wv.y;
        Bs[lk4 + 2][lrow] = wv.z; Bs[lk4 + 3][lrow] = wv.w;
        __syncthreads();

        #pragma unroll
        for (int kk = 0; kk < 8; kk++) {
            float4 a0 = *(const float4*)&As[kk][ty * 8];
            float4 a1 = *(const float4*)&As[kk][ty * 8 + 4];
            float4 b0 = *(const float4*)&Bs[kk][tx * 8];
            float4 b1 = *(const float4*)&Bs[kk][tx * 8 + 4];
            float a[8] = {a0.x, a0.y, a0.z, a0.w, a1.x, a1.y, a1.z, a1.w};
            float b[8] = {b0.x, b0.y, b0.z, b0.w, b1.x, b1.y, b1.z, b1.w};
            #pragma unroll
            for (int i = 0; i < 8; i++)
                #pragma unroll
                for (int j = 0; j < 8; j++)
                    acc[i][j] = fmaf(a[i], b[j], acc[i][j]);
        }
        __syncthreads();
    }

    #pragma unroll
    for (int i = 0; i < 8; i++) {
        int m = m0 + ty * 8 + i;            // global token index = b*T + t
        #pragma unroll
        for (int j = 0; j < 8; j++) {
            int n = n0 + tx * 8 + j;
            float v = acc[i][j] + bias[n];
            if (MODE == 0) {
                int which = n >> 10;        // 0:Q 1:K 2:V
                int c = n & 1023;
                int h = c >> 6;
                int d = c & 63;
                int b = m >> 11;            // m / T  (T = 2048)
                int t = m & 2047;
                float* dst = (which == 0) ? Qo : (which == 1) ? Ko : Vo;
                dst[(((size_t)b * HH + h) * TT + t) * DHH + d] = v;
            } else {
                C[(size_t)m * N + n] = v;
            }
        }
    }
}

// ---------------------------------------------------------------------------
// Flash attention, fp32, causal + key padding mask (mask is int32: nonzero = valid).
// Grid: (T/128, B*H). Block: 128 threads; thread = one query row.
// q and o accumulators in registers; K/V tiles (32 x 64) in smem, broadcast
// reads (uniform j,d per instruction across the warp -> conflict-free).
// Writes Y directly in (B, T, C) layout with C index = h*64 + d.
// ---------------------------------------------------------------------------
__global__ __launch_bounds__(128, 2)
void attn_kernel(const float* __restrict__ Q, const float* __restrict__ K,
                 const float* __restrict__ V, const int* __restrict__ amask,
                 float* __restrict__ Y)
{
    const int bh = blockIdx.y;
    const int b  = bh / HH;
    const int h  = bh % HH;
    const int q  = blockIdx.x * 128 + threadIdx.x;

    __shared__ float Ks[32][64];
    __shared__ float Vs[32][64];
    __shared__ int msk[32];

    const float scale = 0.125f;   // 1/sqrt(64)

    float qr[64];
    {
        const float* Qp = Q + ((size_t)bh * TT + q) * DHH;
        #pragma unroll
        for (int d = 0; d < 64; d += 4) {
            float4 v4 = *(const float4*)(Qp + d);
            qr[d + 0] = v4.x * scale; qr[d + 1] = v4.y * scale;
            qr[d + 2] = v4.z * scale; qr[d + 3] = v4.w * scale;
        }
    }

    float o[64];
    #pragma unroll
    for (int d = 0; d < 64; d++) o[d] = 0.f;
    float m_i = -INFINITY;
    float l   = 0.f;

    const int kv_end = blockIdx.x * 128 + 128;   // exclusive causal bound for block

    for (int kv0 = 0; kv0 < kv_end; kv0 += 32) {
        const float* Kp = K + ((size_t)bh * TT + kv0) * DHH;
        const float* Vp = V + ((size_t)bh * TT + kv0) * DHH;
        // 32*64 floats = 512 float4 per tensor; 128 threads x 4 each, coalesced.
        #pragma unroll
        for (int i = 0; i < 4; i++) {
            int li = i * 128 + threadIdx.x;   // 0..511 float4 index
            int r  = li >> 4;
            int c4 = li & 15;
            ((float4*)&Ks[r][0])[c4] = ((const float4*)(Kp + r * 64))[c4];
            ((float4*)&Vs[r][0])[c4] = ((const float4*)(Vp + r * 64))[c4];
        }
        if (threadIdx.x < 32) msk[threadIdx.x] = amask[(size_t)b * TT + kv0 + threadIdx.x];
        __syncthreads();

        float s[32];
        float tmax = -INFINITY;
        #pragma unroll
        for (int j = 0; j < 32; j++) {
            float a = 0.f;
            #pragma unroll
            for (int d = 0; d < 64; d++) a = fmaf(qr[d], Ks[j][d], a);
            bool valid = ((kv0 + j) <= q) && (msk[j] != 0);
            s[j] = valid ? a : -INFINITY;
            tmax = fmaxf(tmax, s[j]);
        }

        float m_new = fmaxf(m_i, tmax);
        if (m_new != -INFINITY) {
            float alpha = (m_i == -INFINITY) ? 0.f : __expf(m_i - m_new);
            l *= alpha;
            #pragma unroll
            for (int d = 0; d < 64; d++) o[d] *= alpha;
            #pragma unroll
            for (int j = 0; j < 32; j++) {
                float p = __expf(s[j] - m_new);   // -inf -> 0
                l += p;
                #pragma unroll
                for (int d = 0; d < 64; d++) o[d] = fmaf(p, Vs[j][d], o[d]);
            }
            m_i = m_new;
        }
        __syncthreads();
    }

    const float inv = (l > 0.f) ? (1.f / l) : 0.f;
    float* Yp = Y + ((size_t)(b * TT + q)) * DD + h * DHH;
    #pragma unroll
    for (int d = 0; d < 64; d += 4) {
        float4 v4;
        v4.x = o[d + 0] * inv; v4.y = o[d + 1] * inv;
        v4.z = o[d + 2] * inv; v4.w = o[d + 3] * inv;
        *(float4*)(Yp + d) = v4;
    }
}

// ---------------------------------------------------------------------------
extern "C" void kernel_launch(void* const* d_in, const int* in_sizes, int n_in,
                              void* d_out, int out_size)
{
    const float* x      = (const float*)d_in[0];
    const int*   amask  = (const int*)d_in[1];    // bool marshalled as int32
    const float* w_qkv  = (const float*)d_in[2];
    const float* b_qkv  = (const float*)d_in[3];
    const float* w_proj = (const float*)d_in[4];
    const float* b_proj = (const float*)d_in[5];
    float*       out    = (float*)d_out;

    float *Qp, *Kp, *Vp, *Yp;
    cudaGetSymbolAddress((void**)&Qp, g_Q);
    cudaGetSymbolAddress((void**)&Kp, g_K);
    cudaGetSymbolAddress((void**)&Vp, g_V);
    cudaGetSymbolAddress((void**)&Yp, g_Y);

    const int M = BB * TT;   // 8192

    // 1) QKV projection + scatter into (B,H,T,DH)
    {
        dim3 grid(NQKV / 128, M / 128);   // (24, 64)
        gemm_xwT<0><<<grid, 256>>>(x, w_qkv, b_qkv, nullptr, Qp, Kp, Vp,
                                   M, NQKV, DD);
    }

    // 2) Flash attention -> Y in (B,T,C)
    {
        dim3 grid(TT / 128, BB * HH);     // (16, 64)
        attn_kernel<<<grid, 128>>>(Qp, Kp, Vp, amask, Yp);
    }

    // 3) Output projection -> d_out
    {
        dim3 grid(DD / 128, M / 128);     // (8, 64)
        gemm_xwT<1><<<grid, 256>>>(Yp, w_proj, b_proj, out, nullptr, nullptr, nullptr,
                                   M, DD, DD);
    }
}

// round 6
// speedup vs baseline: 1.4321x; 1.4321x over previous
#include <cuda_runtime.h>
#include <math.h>
#include <stdint.h>

// Problem constants
#define BB 4
#define TT 2048
#define DD 1024
#define HH 16
#define DHH 64
#define NQKV (3 * DD)

// Scratch: __device__ globals (allocation-free rule).
__device__ float g_Q[BB * HH * TT * DHH];
__device__ float g_K[BB * HH * TT * DHH];
__device__ float g_V[BB * HH * TT * DHH];
__device__ float g_Y[BB * TT * DD];

// ---------------------------------------------------------------------------
// tf32 helpers
// ---------------------------------------------------------------------------
__device__ __forceinline__ uint32_t f2tf32(float x) {
    uint32_t r;
    asm("cvt.rna.tf32.f32 %0, %1;" : "=r"(r) : "f"(x));
    return r;
}

__device__ __forceinline__ void mma_tf32(float* c, const uint32_t* a, const uint32_t* b) {
    asm volatile(
        "mma.sync.aligned.m16n8k8.row.col.f32.tf32.tf32.f32 "
        "{%0,%1,%2,%3}, {%4,%5,%6,%7}, {%8,%9}, {%0,%1,%2,%3};\n"
        : "+f"(c[0]), "+f"(c[1]), "+f"(c[2]), "+f"(c[3])
        : "r"(a[0]), "r"(a[1]), "r"(a[2]), "r"(a[3]), "r"(b[0]), "r"(b[1]));
}

// ---------------------------------------------------------------------------
// tf32 tensor-core GEMM: C = A @ W^T (+bias).
// A: (M,K) row-major, W: (N,K) row-major.
// Block tile 128x128, K-tile 8, 256 threads (8 warps as 2m x 4n).
// Warp tile 64x32 = 4x4 m16n8k8 mma tiles. Register prefetch of next K-tile.
// MODE 0: scatter epilogue into Q/K/V (B,H,T,DH). MODE 1: plain C.
// ---------------------------------------------------------------------------
template <int MODE>
__global__ __launch_bounds__(256, 2)
void gemm_tf32(const float* __restrict__ A, const float* __restrict__ W,
               const float* __restrict__ bias, float* __restrict__ C,
               float* __restrict__ Qo, float* __restrict__ Ko, float* __restrict__ Vo,
               int M, int N, int K)
{
    __shared__ uint32_t As[8][136];   // [k][m], pad 136 -> conflict-free frag reads
    __shared__ uint32_t Bs[8][136];   // [k][n]

    const int tid  = threadIdx.x;
    const int m0   = blockIdx.y * 128;
    const int n0   = blockIdx.x * 128;

    // Loader mapping: 2 threads per row, 4 floats (16B) each -> coalesced 32B/row.
    const int lrow = tid >> 1;        // 0..127
    const int lk4  = (tid & 1) * 4;   // 0 or 4

    // Warp/fragment mapping
    const int warp = tid >> 5;
    const int lane = tid & 31;
    const int wm0  = (warp >> 2) * 64;   // warp m offset (2 warps in m)
    const int wn0  = (warp & 3) * 32;    // warp n offset (4 warps in n)
    const int g    = lane >> 2;          // groupID 0..7
    const int tg   = lane & 3;           // thread-in-group 0..3

    const float* Aptr = A + (size_t)(m0 + lrow) * K + lk4;
    const float* Wptr = W + (size_t)(n0 + lrow) * K + lk4;

    float acc[4][4][4];
    #pragma unroll
    for (int mt = 0; mt < 4; mt++)
        #pragma unroll
        for (int nt = 0; nt < 4; nt++)
            #pragma unroll
            for (int r = 0; r < 4; r++) acc[mt][nt][r] = 0.f;

    // Prologue load
    float4 av = *(const float4*)(Aptr);
    float4 wv = *(const float4*)(Wptr);

    for (int k0 = 0; k0 < K; k0 += 8) {
        // Store current K-tile (converted to tf32)
        As[lk4 + 0][lrow] = f2tf32(av.x);
        As[lk4 + 1][lrow] = f2tf32(av.y);
        As[lk4 + 2][lrow] = f2tf32(av.z);
        As[lk4 + 3][lrow] = f2tf32(av.w);
        Bs[lk4 + 0][lrow] = f2tf32(wv.x);
        Bs[lk4 + 1][lrow] = f2tf32(wv.y);
        Bs[lk4 + 2][lrow] = f2tf32(wv.z);
        Bs[lk4 + 3][lrow] = f2tf32(wv.w);
        __syncthreads();

        // Prefetch next K-tile into registers
        if (k0 + 8 < K) {
            av = *(const float4*)(Aptr + k0 + 8);
            wv = *(const float4*)(Wptr + k0 + 8);
        }

        // Load fragments from smem
        uint32_t afr[4][4];
        #pragma unroll
        for (int mt = 0; mt < 4; mt++) {
            int m = wm0 + mt * 16 + g;
            afr[mt][0] = As[tg][m];
            afr[mt][1] = As[tg][m + 8];
            afr[mt][2] = As[tg + 4][m];
            afr[mt][3] = As[tg + 4][m + 8];
        }
        uint32_t bfr[4][2];
        #pragma unroll
        for (int nt = 0; nt < 4; nt++) {
            int n = wn0 + nt * 8 + g;
            bfr[nt][0] = Bs[tg][n];
            bfr[nt][1] = Bs[tg + 4][n];
        }

        #pragma unroll
        for (int mt = 0; mt < 4; mt++)
            #pragma unroll
            for (int nt = 0; nt < 4; nt++)
                mma_tf32(acc[mt][nt], afr[mt], bfr[nt]);

        __syncthreads();
    }

    // Epilogue: c0,c1 -> (row=g, cols 2tg,2tg+1); c2,c3 -> (row=g+8, same cols)
    #pragma unroll
    for (int mt = 0; mt < 4; mt++) {
        #pragma unroll
        for (int half = 0; half < 2; half++) {
            int m = m0 + wm0 + mt * 16 + g + half * 8;
            #pragma unroll
            for (int nt = 0; nt < 4; nt++) {
                int n = n0 + wn0 + nt * 8 + 2 * tg;
                float v0 = acc[mt][nt][half * 2 + 0] + bias[n];
                float v1 = acc[mt][nt][half * 2 + 1] + bias[n + 1];
                if (MODE == 0) {
                    int which = n >> 10;
                    int c = n & 1023;
                    int h = c >> 6;
                    int d = c & 63;            // even, d+1 in same head
                    int b = m >> 11;
                    int t = m & 2047;
                    float* dst = (which == 0) ? Qo : (which == 1) ? Ko : Vo;
                    float2* p = (float2*)&dst[(((size_t)b * HH + h) * TT + t) * DHH + d];
                    *p = make_float2(v0, v1);
                } else {
                    float2* p = (float2*)&C[(size_t)m * N + n];
                    *p = make_float2(v0, v1);
                }
            }
        }
    }
}

// ---------------------------------------------------------------------------
// Flash attention, fp32, causal + key padding mask (int32 mask, nonzero=valid).
// Grid: (T/128, B*H). Block: 128 threads; thread = one query row.
// ---------------------------------------------------------------------------
__global__ __launch_bounds__(128, 2)
void attn_kernel(const float* __restrict__ Q, const float* __restrict__ K,
                 const float* __restrict__ V, const int* __restrict__ amask,
                 float* __restrict__ Y)
{
    const int bh = blockIdx.y;
    const int b  = bh / HH;
    const int h  = bh % HH;
    const int q  = blockIdx.x * 128 + threadIdx.x;

    __shared__ float Ks[32][64];
    __shared__ float Vs[32][64];
    __shared__ int msk[32];

    const float scale = 0.125f;   // 1/sqrt(64)

    float qr[64];
    {
        const float* Qp = Q + ((size_t)bh * TT + q) * DHH;
        #pragma unroll
        for (int d = 0; d < 64; d += 4) {
            float4 v4 = *(const float4*)(Qp + d);
            qr[d + 0] = v4.x * scale; qr[d + 1] = v4.y * scale;
            qr[d + 2] = v4.z * scale; qr[d + 3] = v4.w * scale;
        }
    }

    float o[64];
    #pragma unroll
    for (int d = 0; d < 64; d++) o[d] = 0.f;
    float m_i = -INFINITY;
    float l   = 0.f;

    const int kv_end = blockIdx.x * 128 + 128;

    for (int kv0 = 0; kv0 < kv_end; kv0 += 32) {
        const float* Kp = K + ((size_t)bh * TT + kv0) * DHH;
        const float* Vp = V + ((size_t)bh * TT + kv0) * DHH;
        #pragma unroll
        for (int i = 0; i < 4; i++) {
            int li = i * 128 + threadIdx.x;
            int r  = li >> 4;
            int c4 = li & 15;
            ((float4*)&Ks[r][0])[c4] = ((const float4*)(Kp + r * 64))[c4];
            ((float4*)&Vs[r][0])[c4] = ((const float4*)(Vp + r * 64))[c4];
        }
        if (threadIdx.x < 32) msk[threadIdx.x] = amask[(size_t)b * TT + kv0 + threadIdx.x];
        __syncthreads();

        float s[32];
        float tmax = -INFINITY;
        #pragma unroll
        for (int j = 0; j < 32; j++) {
            float a = 0.f;
            #pragma unroll
            for (int d = 0; d < 64; d++) a = fmaf(qr[d], Ks[j][d], a);
            bool valid = ((kv0 + j) <= q) && (msk[j] != 0);
            s[j] = valid ? a : -INFINITY;
            tmax = fmaxf(tmax, s[j]);
        }

        float m_new = fmaxf(m_i, tmax);
        if (m_new != -INFINITY) {
            float alpha = (m_i == -INFINITY) ? 0.f : __expf(m_i - m_new);
            l *= alpha;
            #pragma unroll
            for (int d = 0; d < 64; d++) o[d] *= alpha;
            #pragma unroll
            for (int j = 0; j < 32; j++) {
                float p = __expf(s[j] - m_new);
                l += p;
                #pragma unroll
                for (int d = 0; d < 64; d++) o[d] = fmaf(p, Vs[j][d], o[d]);
            }
            m_i = m_new;
        }
        __syncthreads();
    }

    const float inv = (l > 0.f) ? (1.f / l) : 0.f;
    float* Yp = Y + ((size_t)(b * TT + q)) * DD + h * DHH;
    #pragma unroll
    for (int d = 0; d < 64; d += 4) {
        float4 v4;
        v4.x = o[d + 0] * inv; v4.y = o[d + 1] * inv;
        v4.z = o[d + 2] * inv; v4.w = o[d + 3] * inv;
        *(float4*)(Yp + d) = v4;
    }
}

// ---------------------------------------------------------------------------
extern "C" void kernel_launch(void* const* d_in, const int* in_sizes, int n_in,
                              void* d_out, int out_size)
{
    const float* x      = (const float*)d_in[0];
    const int*   amask  = (const int*)d_in[1];    // bool marshalled as int32
    const float* w_qkv  = (const float*)d_in[2];
    const float* b_qkv  = (const float*)d_in[3];
    const float* w_proj = (const float*)d_in[4];
    const float* b_proj = (const float*)d_in[5];
    float*       out    = (float*)d_out;

    float *Qp, *Kp, *Vp, *Yp;
    cudaGetSymbolAddress((void**)&Qp, g_Q);
    cudaGetSymbolAddress((void**)&Kp, g_K);
    cudaGetSymbolAddress((void**)&Vp, g_V);
    cudaGetSymbolAddress((void**)&Yp, g_Y);

    const int M = BB * TT;   // 8192

    // 1) QKV projection (tf32 tensor cores) + scatter into (B,H,T,DH)
    {
        dim3 grid(NQKV / 128, M / 128);   // (24, 64)
        gemm_tf32<0><<<grid, 256>>>(x, w_qkv, b_qkv, nullptr, Qp, Kp, Vp,
                                    M, NQKV, DD);
    }

    // 2) Flash attention -> Y in (B,T,C)
    {
        dim3 grid(TT / 128, BB * HH);     // (16, 64)
        attn_kernel<<<grid, 128>>>(Qp, Kp, Vp, amask, Yp);
    }

    // 3) Output projection (tf32 tensor cores) -> d_out
    {
        dim3 grid(DD / 128, M / 128);     // (8, 64)
        gemm_tf32<1><<<grid, 256>>>(Yp, w_proj, b_proj, out, nullptr, nullptr, nullptr,
                                    M, DD, DD);
    }
}

// round 8
// speedup vs baseline: 3.1916x; 2.2285x over previous
#include <cuda_runtime.h>
#include <math.h>
#include <stdint.h>

// Problem constants
#define BB 4
#define TT 2048
#define DD 1024
#define HH 16
#define DHH 64
#define NQKV (3 * DD)

// Scratch: __device__ globals (allocation-free rule).
__device__ float g_Q[BB * HH * TT * DHH];
__device__ float g_K[BB * HH * TT * DHH];
__device__ float g_V[BB * HH * TT * DHH];
__device__ float g_Y[BB * TT * DD];

// ---------------------------------------------------------------------------
// tf32 helpers
// ---------------------------------------------------------------------------
__device__ __forceinline__ uint32_t f2tf32(float x) {
    uint32_t r;
    asm("cvt.rna.tf32.f32 %0, %1;" : "=r"(r) : "f"(x));
    return r;
}

__device__ __forceinline__ void mma_tf32(float* c, const uint32_t* a, const uint32_t* b) {
    asm volatile(
        "mma.sync.aligned.m16n8k8.row.col.f32.tf32.tf32.f32 "
        "{%0,%1,%2,%3}, {%4,%5,%6,%7}, {%8,%9}, {%0,%1,%2,%3};\n"
        : "+f"(c[0]), "+f"(c[1]), "+f"(c[2]), "+f"(c[3])
        : "r"(a[0]), "r"(a[1]), "r"(a[2]), "r"(a[3]), "r"(b[0]), "r"(b[1]));
}

// ---------------------------------------------------------------------------
// tf32 tensor-core GEMM: C = A @ W^T (+bias).  (unchanged from R5)
// ---------------------------------------------------------------------------
template <int MODE>
__global__ __launch_bounds__(256, 2)
void gemm_tf32(const float* __restrict__ A, const float* __restrict__ W,
               const float* __restrict__ bias, float* __restrict__ C,
               float* __restrict__ Qo, float* __restrict__ Ko, float* __restrict__ Vo,
               int M, int N, int K)
{
    __shared__ uint32_t As[8][136];
    __shared__ uint32_t Bs[8][136];

    const int tid  = threadIdx.x;
    const int m0   = blockIdx.y * 128;
    const int n0   = blockIdx.x * 128;
    const int lrow = tid >> 1;
    const int lk4  = (tid & 1) * 4;
    const int warp = tid >> 5;
    const int lane = tid & 31;
    const int wm0  = (warp >> 2) * 64;
    const int wn0  = (warp & 3) * 32;
    const int g    = lane >> 2;
    const int tg   = lane & 3;

    const float* Aptr = A + (size_t)(m0 + lrow) * K + lk4;
    const float* Wptr = W + (size_t)(n0 + lrow) * K + lk4;

    float acc[4][4][4];
    #pragma unroll
    for (int mt = 0; mt < 4; mt++)
        #pragma unroll
        for (int nt = 0; nt < 4; nt++)
            #pragma unroll
            for (int r = 0; r < 4; r++) acc[mt][nt][r] = 0.f;

    float4 av = *(const float4*)(Aptr);
    float4 wv = *(const float4*)(Wptr);

    for (int k0 = 0; k0 < K; k0 += 8) {
        As[lk4 + 0][lrow] = f2tf32(av.x);
        As[lk4 + 1][lrow] = f2tf32(av.y);
        As[lk4 + 2][lrow] = f2tf32(av.z);
        As[lk4 + 3][lrow] = f2tf32(av.w);
        Bs[lk4 + 0][lrow] = f2tf32(wv.x);
        Bs[lk4 + 1][lrow] = f2tf32(wv.y);
        Bs[lk4 + 2][lrow] = f2tf32(wv.z);
        Bs[lk4 + 3][lrow] = f2tf32(wv.w);
        __syncthreads();

        if (k0 + 8 < K) {
            av = *(const float4*)(Aptr + k0 + 8);
            wv = *(const float4*)(Wptr + k0 + 8);
        }

        uint32_t afr[4][4];
        #pragma unroll
        for (int mt = 0; mt < 4; mt++) {
            int m = wm0 + mt * 16 + g;
            afr[mt][0] = As[tg][m];
            afr[mt][1] = As[tg][m + 8];
            afr[mt][2] = As[tg + 4][m];
            afr[mt][3] = As[tg + 4][m + 8];
        }
        uint32_t bfr[4][2];
        #pragma unroll
        for (int nt = 0; nt < 4; nt++) {
            int n = wn0 + nt * 8 + g;
            bfr[nt][0] = Bs[tg][n];
            bfr[nt][1] = Bs[tg + 4][n];
        }

        #pragma unroll
        for (int mt = 0; mt < 4; mt++)
            #pragma unroll
            for (int nt = 0; nt < 4; nt++)
                mma_tf32(acc[mt][nt], afr[mt], bfr[nt]);

        __syncthreads();
    }

    #pragma unroll
    for (int mt = 0; mt < 4; mt++) {
        #pragma unroll
        for (int half = 0; half < 2; half++) {
            int m = m0 + wm0 + mt * 16 + g + half * 8;
            #pragma unroll
            for (int nt = 0; nt < 4; nt++) {
                int n = n0 + wn0 + nt * 8 + 2 * tg;
                float v0 = acc[mt][nt][half * 2 + 0] + bias[n];
                float v1 = acc[mt][nt][half * 2 + 1] + bias[n + 1];
                if (MODE == 0) {
                    int which = n >> 10;
                    int c = n & 1023;
                    int h = c >> 6;
                    int d = c & 63;
                    int b = m >> 11;
                    int t = m & 2047;
                    float* dst = (which == 0) ? Qo : (which == 1) ? Ko : Vo;
                    float2* p = (float2*)&dst[(((size_t)b * HH + h) * TT + t) * DHH + d];
                    *p = make_float2(v0, v1);
                } else {
                    float2* p = (float2*)&C[(size_t)m * N + n];
                    *p = make_float2(v0, v1);
                }
            }
        }
    }
}

// ---------------------------------------------------------------------------
// Tensor-core flash attention (tf32 mma), causal + key padding mask.
// Grid: (T/64, B*H), heavy tiles launched first. Block: 128 threads, 4 warps.
// Warp w owns query rows [16w, 16w+16) of the 64-row Q tile.
// Smem (dynamic): Ks[64][68] u32(tf32), Vs[64][68], Ps[4][16][68], msk[64].
// ---------------------------------------------------------------------------
#define BM 64
#define BN 64
#define LDS_K 68
#define OFF_KS 0
#define OFF_VS (64 * LDS_K)
#define OFF_PS (2 * 64 * LDS_K)
#define OFF_MSK (3 * 64 * LDS_K)
#define SMEM_U32 (3 * 64 * LDS_K + 64)
#define ATTN_SMEM_BYTES (SMEM_U32 * 4)

__global__ __launch_bounds__(128, 2)
void attn_tc(const float* __restrict__ Q, const float* __restrict__ K,
             const float* __restrict__ V, const int* __restrict__ amask,
             float* __restrict__ Y)
{
    extern __shared__ uint32_t sm[];
    uint32_t* Ks = sm + OFF_KS;
    uint32_t* Vs = sm + OFF_VS;
    uint32_t* Ps = sm + OFF_PS;
    int* msk = (int*)(sm + OFF_MSK);

    const int bh = blockIdx.y;
    const int b  = bh / HH;
    const int h  = bh % HH;
    const int q0 = (gridDim.x - 1 - blockIdx.x) * BM;   // heavy tiles first

    const int tid  = threadIdx.x;
    const int warp = tid >> 5;
    const int lane = tid & 31;
    const int g    = lane >> 2;
    const int tg   = lane & 3;
    const int wm   = warp * 16;
    uint32_t* Pw = Ps + warp * 16 * LDS_K;

    // ---- Stage Q tile (scaled, tf32) through Ks, then load frags ----
    {
        const float* Qg = Q + ((size_t)bh * TT + q0) * DHH;
        #pragma unroll
        for (int i = 0; i < 8; i++) {
            int li = i * 128 + tid;         // 0..1023 float4
            int r  = li >> 4;
            int c4 = li & 15;
            float4 v = ((const float4*)(Qg + r * 64))[c4];
            uint32_t* dst = &Ks[r * LDS_K + c4 * 4];
            dst[0] = f2tf32(v.x * 0.125f); dst[1] = f2tf32(v.y * 0.125f);
            dst[2] = f2tf32(v.z * 0.125f); dst[3] = f2tf32(v.w * 0.125f);
        }
    }
    __syncthreads();

    uint32_t qf[8][4];
    #pragma unroll
    for (int kt = 0; kt < 8; kt++) {
        qf[kt][0] = Ks[(wm + g)     * LDS_K + kt * 8 + tg];
        qf[kt][1] = Ks[(wm + g + 8) * LDS_K + kt * 8 + tg];
        qf[kt][2] = Ks[(wm + g)     * LDS_K + kt * 8 + tg + 4];
        qf[kt][3] = Ks[(wm + g + 8) * LDS_K + kt * 8 + tg + 4];
    }
    __syncthreads();

    float O[8][4];
    #pragma unroll
    for (int nt = 0; nt < 8; nt++)
        #pragma unroll
        for (int r = 0; r < 4; r++) O[nt][r] = 0.f;

    float m0 = -INFINITY, m1 = -INFINITY;   // row g, row g+8 (per-thread rows)
    float l0 = 0.f, l1 = 0.f;               // per-thread partial row sums

    const int qrow0 = q0 + wm + g;
    const int qrow1 = qrow0 + 8;
    const int ntiles = q0 / BN + 1;

    for (int it = 0; it < ntiles; it++) {
        const int kv0 = it * BN;
        // ---- Load K/V tiles (tf32) + mask ----
        {
            const float* Kg = K + ((size_t)bh * TT + kv0) * DHH;
            const float* Vg = V + ((size_t)bh * TT + kv0) * DHH;
            #pragma unroll
            for (int i = 0; i < 8; i++) {
                int li = i * 128 + tid;
                int r  = li >> 4;
                int c4 = li & 15;
                float4 kv4 = ((const float4*)(Kg + r * 64))[c4];
                float4 vv4 = ((const float4*)(Vg + r * 64))[c4];
                uint32_t* dk = &Ks[r * LDS_K + c4 * 4];
                uint32_t* dv = &Vs[r * LDS_K + c4 * 4];
                dk[0] = f2tf32(kv4.x); dk[1] = f2tf32(kv4.y);
                dk[2] = f2tf32(kv4.z); dk[3] = f2tf32(kv4.w);
                dv[0] = f2tf32(vv4.x); dv[1] = f2tf32(vv4.y);
                dv[2] = f2tf32(vv4.z); dv[3] = f2tf32(vv4.w);
            }
            if (tid < 64) msk[tid] = amask[(size_t)b * TT + kv0 + tid];
        }
        __syncthreads();

        // ---- S = Q @ K^T ----
        float S[8][4];
        #pragma unroll
        for (int nt = 0; nt < 8; nt++)
            #pragma unroll
            for (int r = 0; r < 4; r++) S[nt][r] = 0.f;

        #pragma unroll
        for (int nt = 0; nt < 8; nt++) {
            #pragma unroll
            for (int kt = 0; kt < 8; kt++) {
                uint32_t bfr[2];
                bfr[0] = Ks[(nt * 8 + g) * LDS_K + kt * 8 + tg];
                bfr[1] = Ks[(nt * 8 + g) * LDS_K + kt * 8 + tg + 4];
                mma_tf32(S[nt], qf[kt], bfr);
            }
        }

        // ---- Mask + online softmax ----
        float tmax0 = -INFINITY, tmax1 = -INFINITY;
        #pragma unroll
        for (int nt = 0; nt < 8; nt++) {
            #pragma unroll
            for (int e = 0; e < 2; e++) {
                int kc = nt * 8 + 2 * tg + e;
                int kv = kv0 + kc;
                bool mk = (msk[kc] != 0);
                S[nt][e]     = (mk && kv <= qrow0) ? S[nt][e]     : -INFINITY;
                S[nt][2 + e] = (mk && kv <= qrow1) ? S[nt][2 + e] : -INFINITY;
                tmax0 = fmaxf(tmax0, S[nt][e]);
                tmax1 = fmaxf(tmax1, S[nt][2 + e]);
            }
        }
        #pragma unroll
        for (int sh = 1; sh <= 2; sh <<= 1) {
            tmax0 = fmaxf(tmax0, __shfl_xor_sync(0xffffffffu, tmax0, sh));
            tmax1 = fmaxf(tmax1, __shfl_xor_sync(0xffffffffu, tmax1, sh));
        }

        float mn0 = fmaxf(m0, tmax0);
        float mn1 = fmaxf(m1, tmax1);
        bool live0 = (mn0 != -INFINITY);
        bool live1 = (mn1 != -INFINITY);
        float alpha0 = 1.f, alpha1 = 1.f;
        if (live0) { alpha0 = (m0 == -INFINITY) ? 0.f : __expf(m0 - mn0); m0 = mn0; }
        if (live1) { alpha1 = (m1 == -INFINITY) ? 0.f : __expf(m1 - mn1); m1 = mn1; }

        float ls0 = 0.f, ls1 = 0.f;
        #pragma unroll
        for (int nt = 0; nt < 8; nt++) {
            float p00 = live0 ? __expf(S[nt][0] - mn0) : 0.f;
            float p01 = live0 ? __expf(S[nt][1] - mn0) : 0.f;
            float p10 = live1 ? __expf(S[nt][2] - mn1) : 0.f;
            float p11 = live1 ? __expf(S[nt][3] - mn1) : 0.f;
            ls0 += p00 + p01;
            ls1 += p10 + p11;
            int c = nt * 8 + 2 * tg;
            Pw[g * LDS_K + c]           = f2tf32(p00);
            Pw[g * LDS_K + c + 1]       = f2tf32(p01);
            Pw[(g + 8) * LDS_K + c]     = f2tf32(p10);
            Pw[(g + 8) * LDS_K + c + 1] = f2tf32(p11);
        }
        l0 = l0 * alpha0 + ls0;
        l1 = l1 * alpha1 + ls1;
        #pragma unroll
        for (int nt = 0; nt < 8; nt++) {
            O[nt][0] *= alpha0; O[nt][1] *= alpha0;
            O[nt][2] *= alpha1; O[nt][3] *= alpha1;
        }
        __syncwarp();

        // ---- O += P @ V ----
        #pragma unroll
        for (int kt = 0; kt < 8; kt++) {
            uint32_t afr[4];
            afr[0] = Pw[g * LDS_K + kt * 8 + tg];
            afr[1] = Pw[(g + 8) * LDS_K + kt * 8 + tg];
            afr[2] = Pw[g * LDS_K + kt * 8 + tg + 4];
            afr[3] = Pw[(g + 8) * LDS_K + kt * 8 + tg + 4];
            #pragma unroll
            for (int nt = 0; nt < 8; nt++) {
                uint32_t bfr[2];
                bfr[0] = Vs[(kt * 8 + tg)     * LDS_K + nt * 8 + g];
                bfr[1] = Vs[(kt * 8 + tg + 4) * LDS_K + nt * 8 + g];
                mma_tf32(O[nt], afr, bfr);
            }
        }
        __syncthreads();
    }

    // ---- Epilogue: normalize and write Y (B,T,C), C col = h*64 + d ----
    #pragma unroll
    for (int sh = 1; sh <= 2; sh <<= 1) {
        l0 += __shfl_xor_sync(0xffffffffu, l0, sh);
        l1 += __shfl_xor_sync(0xffffffffu, l1, sh);
    }
    const float inv0 = (l0 > 0.f) ? (1.f / l0) : 0.f;
    const float inv1 = (l1 > 0.f) ? (1.f / l1) : 0.f;

    float* Y0 = Y + ((size_t)(b * TT + qrow0)) * DD + h * DHH;
    float* Y1 = Y + ((size_t)(b * TT + qrow1)) * DD + h * DHH;
    #pragma unroll
    for (int nt = 0; nt < 8; nt++) {
        int d = nt * 8 + 2 * tg;
        *(float2*)(Y0 + d) = make_float2(O[nt][0] * inv0, O[nt][1] * inv0);
        *(float2*)(Y1 + d) = make_float2(O[nt][2] * inv1, O[nt][3] * inv1);
    }
}

// ---------------------------------------------------------------------------
extern "C" void kernel_launch(void* const* d_in, const int* in_sizes, int n_in,
                              void* d_out, int out_size)
{
    const float* x      = (const float*)d_in[0];
    const int*   amask  = (const int*)d_in[1];    // bool marshalled as int32
    const float* w_qkv  = (const float*)d_in[2];
    const float* b_qkv  = (const float*)d_in[3];
    const float* w_proj = (const float*)d_in[4];
    const float* b_proj = (const float*)d_in[5];
    float*       out    = (float*)d_out;

    float *Qp, *Kp, *Vp, *Yp;
    cudaGetSymbolAddress((void**)&Qp, g_Q);
    cudaGetSymbolAddress((void**)&Kp, g_K);
    cudaGetSymbolAddress((void**)&Vp, g_V);
    cudaGetSymbolAddress((void**)&Yp, g_Y);

    static bool attr_set = false;
    if (!attr_set) {
        cudaFuncSetAttribute(attn_tc, cudaFuncAttributeMaxDynamicSharedMemorySize,
                             ATTN_SMEM_BYTES);
        attr_set = true;
    }

    const int M = BB * TT;   // 8192

    // 1) QKV projection (tf32 tensor cores) + scatter into (B,H,T,DH)
    {
        dim3 grid(NQKV / 128, M / 128);   // (24, 64)
        gemm_tf32<0><<<grid, 256>>>(x, w_qkv, b_qkv, nullptr, Qp, Kp, Vp,
                                    M, NQKV, DD);
    }

    // 2) Tensor-core flash attention -> Y in (B,T,C)
    {
        dim3 grid(TT / BM, BB * HH);      // (32, 64)
        attn_tc<<<grid, 128, ATTN_SMEM_BYTES>>>(Qp, Kp, Vp, amask, Yp);
    }

    // 3) Output projection (tf32 tensor cores) -> d_out
    {
        dim3 grid(DD / 128, M / 128);     // (8, 64)
        gemm_tf32<1><<<grid, 256>>>(Yp, w_proj, b_proj, out, nullptr, nullptr, nullptr,
                                    M, DD, DD);
    }
}